// round 1
// baseline (speedup 1.0000x reference)
#include <cuda_runtime.h>
#include <math.h>

#define SEQ    4096
#define BATCH  4
#define HID    1024
#define NH     16
#define HD     64
#define BHD    (BATCH * NH)     // 64
#define WIN    257
#define HALF   128
#define MINSC  (-1e9f)

// ---------------- scratch (device globals; no allocation allowed) ------------
// head-split layout: [bh][seq][hd]
__device__ float g_q[(size_t)BHD * SEQ * HD];
__device__ float g_k[(size_t)BHD * SEQ * HD];
__device__ float g_v[(size_t)BHD * SEQ * HD];

// ---------------- projection GEMM: C[r][h] = sum_j X[r][j] * W[h][j] + b[h] --
// X rows r = s*BATCH + b (natural [S,B,H] layout). Epilogue scatters into
// head-split [bh][s][d] layout.
#define BM 128
#define BN 128
#define BK 8

__global__ __launch_bounds__(256) void proj_kernel(
    const float* __restrict__ xq, const float* __restrict__ xk, const float* __restrict__ xv,
    const float* __restrict__ wq, const float* __restrict__ wk, const float* __restrict__ wv,
    const float* __restrict__ bq, const float* __restrict__ bk, const float* __restrict__ bv)
{
    const int z = blockIdx.z;
    const float* X = (z == 0) ? xq : (z == 1) ? xk : xv;
    const float* W = (z == 0) ? wq : (z == 1) ? wk : wv;
    const float* B = (z == 0) ? bq : (z == 1) ? bk : bv;
    float*       O = (z == 0) ? g_q : (z == 1) ? g_k : g_v;

    __shared__ float As[BK][BM];
    __shared__ float Bs[BK][BN];

    const int tid = threadIdx.x;          // 0..255
    const int tx  = tid & 15;             // 0..15
    const int ty  = tid >> 4;             // 0..15
    const int bm0 = blockIdx.y * BM;      // row tile (16384 rows)
    const int bn0 = blockIdx.x * BN;      // col tile (1024 cols)

    const int lr = tid >> 1;              // 0..127
    const int lc = (tid & 1) * 4;         // 0 or 4

    float acc[8][8];
#pragma unroll
    for (int i = 0; i < 8; i++)
#pragma unroll
        for (int j = 0; j < 8; j++) acc[i][j] = 0.f;

    for (int k0 = 0; k0 < HID; k0 += BK) {
        const float4 xa = *(const float4*)(X + (size_t)(bm0 + lr) * HID + k0 + lc);
        const float4 wa = *(const float4*)(W + (size_t)(bn0 + lr) * HID + k0 + lc);
        __syncthreads();
        As[lc + 0][lr] = xa.x; As[lc + 1][lr] = xa.y;
        As[lc + 2][lr] = xa.z; As[lc + 3][lr] = xa.w;
        Bs[lc + 0][lr] = wa.x; Bs[lc + 1][lr] = wa.y;
        Bs[lc + 2][lr] = wa.z; Bs[lc + 3][lr] = wa.w;
        __syncthreads();
#pragma unroll
        for (int kk = 0; kk < BK; kk++) {
            float a[8], b[8];
            const float4 a0 = *(const float4*)&As[kk][ty * 8];
            const float4 a1 = *(const float4*)&As[kk][ty * 8 + 4];
            const float4 b0 = *(const float4*)&Bs[kk][tx * 8];
            const float4 b1 = *(const float4*)&Bs[kk][tx * 8 + 4];
            a[0]=a0.x; a[1]=a0.y; a[2]=a0.z; a[3]=a0.w;
            a[4]=a1.x; a[5]=a1.y; a[6]=a1.z; a[7]=a1.w;
            b[0]=b0.x; b[1]=b0.y; b[2]=b0.z; b[3]=b0.w;
            b[4]=b1.x; b[5]=b1.y; b[6]=b1.z; b[7]=b1.w;
#pragma unroll
            for (int i = 0; i < 8; i++)
#pragma unroll
                for (int j = 0; j < 8; j++) acc[i][j] += a[i] * b[j];
        }
    }

    // epilogue: add bias, scatter to head-split layout
#pragma unroll
    for (int i = 0; i < 8; i++) {
        const int r = bm0 + ty * 8 + i;
        const int s = r >> 2;            // r = s*BATCH + b
        const int b = r & 3;
#pragma unroll
        for (int j = 0; j < 8; j++) {
            const int h    = bn0 + tx * 8 + j;
            const int head = h >> 6;
            const int d    = h & 63;
            const float v  = acc[i][j] + B[h];
            O[((size_t)(b * NH + head) * SEQ + s) * HD + d] = v;
        }
    }
}

// ---------------- local attention --------------------------------------------
#define TS     32
#define WROWS  (TS + 2 * HALF)   // 288
#define KST    65                // K row stride (conflict-free scalar reads)
#define VST    66                // V row stride (aligned float2 reads)
#define PST    260
#define SMEM_FLOATS (WROWS * KST + WROWS * VST + TS * HD + TS * PST)
#define SMEM_BYTES  (SMEM_FLOATS * 4)   // 192384

__global__ __launch_bounds__(256) void attn_kernel(
    const unsigned char* __restrict__ mask,
    float* __restrict__ out, float* __restrict__ probs)
{
    const int bh   = blockIdx.y;
    const int s0   = blockIdx.x * TS;
    const int b    = bh >> 4;
    const int head = bh & 15;

    const float* Kp = g_k + (size_t)bh * SEQ * HD;
    const float* Vp = g_v + (size_t)bh * SEQ * HD;
    const float* Qp = g_q + (size_t)bh * SEQ * HD;

    extern __shared__ float sh[];
    float* Ksh = sh;
    float* Vsh = Ksh + WROWS * KST;
    float* Qsh = Vsh + WROWS * VST;
    float* Psh = Qsh + TS * HD;

    const int tid = threadIdx.x;
    const int base = s0 - HALF;

    // stage K/V window (zero-fill out of range)
    for (int idx = tid; idx < WROWS * (HD / 4); idx += 256) {
        const int row = idx >> 4;
        const int c4  = (idx & 15) * 4;
        const int t   = base + row;
        float4 kv = make_float4(0.f, 0.f, 0.f, 0.f);
        float4 vv = make_float4(0.f, 0.f, 0.f, 0.f);
        if (t >= 0 && t < SEQ) {
            kv = *(const float4*)(Kp + (size_t)t * HD + c4);
            vv = *(const float4*)(Vp + (size_t)t * HD + c4);
        }
        float* kr = Ksh + row * KST + c4;
        kr[0] = kv.x; kr[1] = kv.y; kr[2] = kv.z; kr[3] = kv.w;
        float* vr = Vsh + row * VST + c4;
        vr[0] = vv.x; vr[1] = vv.y; vr[2] = vv.z; vr[3] = vv.w;
    }
    // stage Q tile
    for (int idx = tid; idx < TS * (HD / 4); idx += 256) {
        const int row = idx >> 4;
        const int c4  = (idx & 15) * 4;
        *(float4*)(Qsh + row * HD + c4) =
            *(const float4*)(Qp + (size_t)(s0 + row) * HD + c4);
    }
    __syncthreads();

    const int warp = tid >> 5;
    const int lane = tid & 31;

    for (int jq = 0; jq < 4; jq++) {
        const int qi = warp * 4 + jq;
        const int s  = s0 + qi;

        // ---- scores: lane handles offsets oi = lane + 32*j ----
        float sc[9];
#pragma unroll
        for (int j = 0; j < 9; j++) sc[j] = 0.f;

#pragma unroll
        for (int dc = 0; dc < 4; dc++) {
            float qreg[16];
#pragma unroll
            for (int dd = 0; dd < 16; dd++) qreg[dd] = Qsh[qi * HD + dc * 16 + dd];
#pragma unroll
            for (int j = 0; j < 9; j++) {
                const int oi = lane + 32 * j;
                if (oi < WIN) {
                    const float* kr = Ksh + (qi + oi) * KST + dc * 16;
                    float a = 0.f;
#pragma unroll
                    for (int dd = 0; dd < 16; dd++) a += qreg[dd] * kr[dd];
                    sc[j] += a;
                }
            }
        }

        // ---- validity + masked scores ----
        float sval[9];
        bool  vld[9];
#pragma unroll
        for (int j = 0; j < 9; j++) {
            const int oi = lane + 32 * j;
            if (oi < WIN) {
                const int t = s + oi - HALF;
                const bool v = (t >= 0) && (t < SEQ) && (mask[t * BATCH + b] == 0);
                vld[j]  = v;
                sval[j] = v ? sc[j] : MINSC;
            } else {
                vld[j]  = false;
                sval[j] = -1e30f;   // never the max; exp underflows to 0
            }
        }

        // ---- softmax over the 257 offsets (warp-wide) ----
        float m = sval[0];
#pragma unroll
        for (int j = 1; j < 9; j++) m = fmaxf(m, sval[j]);
#pragma unroll
        for (int o = 16; o > 0; o >>= 1) m = fmaxf(m, __shfl_xor_sync(0xffffffffu, m, o));

        float pv[9];
        float lsum = 0.f;
#pragma unroll
        for (int j = 0; j < 9; j++) { pv[j] = __expf(sval[j] - m); lsum += pv[j]; }
#pragma unroll
        for (int o = 16; o > 0; o >>= 1) lsum += __shfl_xor_sync(0xffffffffu, lsum, o);
        const float inv = 1.f / lsum;

        float* prow = probs + ((size_t)bh * SEQ + s) * WIN;
#pragma unroll
        for (int j = 0; j < 9; j++) {
            const int oi = lane + 32 * j;
            if (oi < WIN) {
                const float p = vld[j] ? pv[j] * inv : 0.f;
                Psh[qi * PST + oi] = p;
                prow[oi] = p;
            }
        }
        __syncwarp();

        // ---- aggregation: out[d] = sum_o p_o * V[s+o-128][d], lane -> d=2l,2l+1
        const int d0 = 2 * lane;
        float acc0 = 0.f, acc1 = 0.f;
        const float* vbase = Vsh + qi * VST + d0;
        const float* pqr   = Psh + qi * PST;
#pragma unroll 4
        for (int oi = 0; oi < WIN; oi++) {
            const float  p  = pqr[oi];
            const float2 vv = *(const float2*)(vbase + oi * VST);
            acc0 += p * vv.x;
            acc1 += p * vv.y;
        }
        float* orow = out + ((size_t)s * BATCH + b) * HID + head * HD;
        *(float2*)(orow + d0) = make_float2(acc0, acc1);
        __syncwarp();
    }
}

// ---------------- launch ------------------------------------------------------
extern "C" void kernel_launch(void* const* d_in, const int* in_sizes, int n_in,
                              void* d_out, int out_size)
{
    const float* q_in = (const float*)d_in[0];
    const float* k_in = (const float*)d_in[1];
    const float* v_in = (const float*)d_in[2];
    const unsigned char* mask = (const unsigned char*)d_in[3];
    const float* Wq = (const float*)d_in[4];
    const float* bq = (const float*)d_in[5];
    const float* Wk = (const float*)d_in[6];
    const float* bk = (const float*)d_in[7];
    const float* Wv = (const float*)d_in[8];
    const float* bv = (const float*)d_in[9];

    float* out   = (float*)d_out;
    float* probs = out + (size_t)SEQ * BATCH * HID;

    cudaFuncSetAttribute(attn_kernel, cudaFuncAttributeMaxDynamicSharedMemorySize,
                         SMEM_BYTES);

    dim3 g1(HID / BN, (SEQ * BATCH) / BM, 3);
    proj_kernel<<<g1, 256>>>(q_in, k_in, v_in, Wq, Wk, Wv, bq, bk, bv);

    dim3 g2(SEQ / TS, BHD);
    attn_kernel<<<g2, 256, SMEM_BYTES>>>(mask, out, probs);
}

// round 2
// speedup vs baseline: 1.2513x; 1.2513x over previous
#include <cuda_runtime.h>
#include <math.h>

#define SEQ    4096
#define BATCH  4
#define HID    1024
#define NH     16
#define HD     64
#define BHD    (BATCH * NH)     // 64
#define WIN    257
#define HALF   128
#define MINSC  (-1e9f)

// ---------------- scratch (device globals; no allocation allowed) ------------
__device__ float g_q[(size_t)BHD * SEQ * HD];
__device__ float g_k[(size_t)BHD * SEQ * HD];
__device__ float g_v[(size_t)BHD * SEQ * HD];

// ---------------- projection GEMM (unchanged this round) ---------------------
#define BM 128
#define BN 128
#define BK 8

__global__ __launch_bounds__(256) void proj_kernel(
    const float* __restrict__ xq, const float* __restrict__ xk, const float* __restrict__ xv,
    const float* __restrict__ wq, const float* __restrict__ wk, const float* __restrict__ wv,
    const float* __restrict__ bq, const float* __restrict__ bk, const float* __restrict__ bv)
{
    const int z = blockIdx.z;
    const float* X = (z == 0) ? xq : (z == 1) ? xk : xv;
    const float* W = (z == 0) ? wq : (z == 1) ? wk : wv;
    const float* B = (z == 0) ? bq : (z == 1) ? bk : bv;
    float*       O = (z == 0) ? g_q : (z == 1) ? g_k : g_v;

    __shared__ float As[BK][BM];
    __shared__ float Bs[BK][BN];

    const int tid = threadIdx.x;
    const int tx  = tid & 15;
    const int ty  = tid >> 4;
    const int bm0 = blockIdx.y * BM;
    const int bn0 = blockIdx.x * BN;

    const int lr = tid >> 1;
    const int lc = (tid & 1) * 4;

    float acc[8][8];
#pragma unroll
    for (int i = 0; i < 8; i++)
#pragma unroll
        for (int j = 0; j < 8; j++) acc[i][j] = 0.f;

    for (int k0 = 0; k0 < HID; k0 += BK) {
        const float4 xa = *(const float4*)(X + (size_t)(bm0 + lr) * HID + k0 + lc);
        const float4 wa = *(const float4*)(W + (size_t)(bn0 + lr) * HID + k0 + lc);
        __syncthreads();
        As[lc + 0][lr] = xa.x; As[lc + 1][lr] = xa.y;
        As[lc + 2][lr] = xa.z; As[lc + 3][lr] = xa.w;
        Bs[lc + 0][lr] = wa.x; Bs[lc + 1][lr] = wa.y;
        Bs[lc + 2][lr] = wa.z; Bs[lc + 3][lr] = wa.w;
        __syncthreads();
#pragma unroll
        for (int kk = 0; kk < BK; kk++) {
            float a[8], b[8];
            const float4 a0 = *(const float4*)&As[kk][ty * 8];
            const float4 a1 = *(const float4*)&As[kk][ty * 8 + 4];
            const float4 b0 = *(const float4*)&Bs[kk][tx * 8];
            const float4 b1 = *(const float4*)&Bs[kk][tx * 8 + 4];
            a[0]=a0.x; a[1]=a0.y; a[2]=a0.z; a[3]=a0.w;
            a[4]=a1.x; a[5]=a1.y; a[6]=a1.z; a[7]=a1.w;
            b[0]=b0.x; b[1]=b0.y; b[2]=b0.z; b[3]=b0.w;
            b[4]=b1.x; b[5]=b1.y; b[6]=b1.z; b[7]=b1.w;
#pragma unroll
            for (int i = 0; i < 8; i++)
#pragma unroll
                for (int j = 0; j < 8; j++) acc[i][j] += a[i] * b[j];
        }
    }

#pragma unroll
    for (int i = 0; i < 8; i++) {
        const int r = bm0 + ty * 8 + i;
        const int s = r >> 2;
        const int b = r & 3;
#pragma unroll
        for (int j = 0; j < 8; j++) {
            const int h    = bn0 + tx * 8 + j;
            const int head = h >> 6;
            const int d    = h & 63;
            const float v  = acc[i][j] + B[h];
            O[((size_t)(b * NH + head) * SEQ + s) * HD + d] = v;
        }
    }
}

// ---------------- local attention v2: register-blocked GEMM style ------------
#define TQ   64
#define WR   320                 // TQ + 2*HALF
#define KST  68                  // K/V row stride (floats), 16B-aligned, %32==4
#define QST  68
#define PST  324                 // score/prob row stride, 16B-aligned, %32==4
#define NFL  (WR * KST + TQ * QST + TQ * PST + 128)
#define ATT_SMEM_BYTES (NFL * 4) // 187904 B

__global__ __launch_bounds__(512) void attn_kernel(
    const unsigned char* __restrict__ mask,
    float* __restrict__ out, float* __restrict__ probs)
{
    const int bh   = blockIdx.y;
    const int s0   = blockIdx.x * TQ;
    const int b    = bh >> 4;
    const int head = bh & 15;
    const int base = s0 - HALF;

    const float* Kp = g_k + (size_t)bh * SEQ * HD;
    const float* Vp = g_v + (size_t)bh * SEQ * HD;
    const float* Qp = g_q + (size_t)bh * SEQ * HD;

    extern __shared__ float sh[];
    float* Ksh = sh;                       // WR x KST  (later reused for V, then partials)
    float* Qsh = Ksh + WR * KST;           // TQ x QST
    float* Psh = Qsh + TQ * QST;           // TQ x PST  (scores -> probs)
    unsigned char* msh = (unsigned char*)(Psh + TQ * PST);  // WR bytes

    const int tid = threadIdx.x;

    // ---- stage mask/validity, K window, Q tile ----
    for (int o = tid; o < WR; o += 512) {
        const int t = base + o;
        msh[o] = (t >= 0 && t < SEQ && mask[t * BATCH + b] == 0) ? 1 : 0;
    }
    for (int idx = tid; idx < WR * 16; idx += 512) {
        const int row = idx >> 4;
        const int c4  = (idx & 15) * 4;
        const int t   = base + row;
        float4 kv = make_float4(0.f, 0.f, 0.f, 0.f);
        if (t >= 0 && t < SEQ) kv = *(const float4*)(Kp + (size_t)t * HD + c4);
        *(float4*)(Ksh + row * KST + c4) = kv;
    }
    for (int idx = tid; idx < TQ * 16; idx += 512) {
        const int row = idx >> 4;
        const int c4  = (idx & 15) * 4;
        *(float4*)(Qsh + row * QST + c4) =
            *(const float4*)(Qp + (size_t)(s0 + row) * HD + c4);
    }
    __syncthreads();

    const int warp = tid >> 5;
    const int lane = tid & 31;

    // ---- GEMM1: S[64 x 320] = Q[64 x 64] * K^T ----
    // warps: 2 q-groups x 8 o-groups; warp tile 32q x 40o
    // lanes: lq = lane&3 (q), lo = lane>>2 (o); thread tile 8q x 5o
    {
        const int wq = warp >> 3;          // 0..1
        const int wo = warp & 7;           // 0..7
        const int lq = lane & 3;
        const int lo = lane >> 2;
        const int qb = wq * 32 + lq;       // rows qb + 4i
        const int ob = wo * 40 + lo;       // cols ob + 8j

        float acc[8][5];
#pragma unroll
        for (int i = 0; i < 8; i++)
#pragma unroll
            for (int j = 0; j < 5; j++) acc[i][j] = 0.f;

#pragma unroll 2
        for (int dc = 0; dc < 16; dc++) {
            const int d = dc * 4;
            float4 Qv[8], Kv[5];
#pragma unroll
            for (int i = 0; i < 8; i++)
                Qv[i] = *(const float4*)(Qsh + (qb + 4 * i) * QST + d);
#pragma unroll
            for (int j = 0; j < 5; j++)
                Kv[j] = *(const float4*)(Ksh + (ob + 8 * j) * KST + d);
#pragma unroll
            for (int i = 0; i < 8; i++)
#pragma unroll
                for (int j = 0; j < 5; j++) {
                    acc[i][j] += Qv[i].x * Kv[j].x;
                    acc[i][j] += Qv[i].y * Kv[j].y;
                    acc[i][j] += Qv[i].z * Kv[j].z;
                    acc[i][j] += Qv[i].w * Kv[j].w;
                }
        }

        // masked epilogue -> Psh (scores)
#pragma unroll
        for (int i = 0; i < 8; i++) {
            const int q = qb + 4 * i;
#pragma unroll
            for (int j = 0; j < 5; j++) {
                const int o = ob + 8 * j;
                float s;
                if (o < q || o > q + 256)      s = -1e30f;   // outside window band
                else if (!msh[o])              s = MINSC;    // OOB / masked key
                else                           s = acc[i][j];
                Psh[q * PST + o] = s;
            }
        }
    }
    __syncthreads();

    // ---- load V window into the K buffer (issue LDGs before softmax math) ----
    for (int idx = tid; idx < WR * 16; idx += 512) {
        const int row = idx >> 4;
        const int c4  = (idx & 15) * 4;
        const int t   = base + row;
        float4 vv = make_float4(0.f, 0.f, 0.f, 0.f);
        if (t >= 0 && t < SEQ) vv = *(const float4*)(Vp + (size_t)t * HD + c4);
        *(float4*)(Ksh + row * KST + c4) = vv;
    }

    // ---- softmax: each warp owns rows warp*4 .. warp*4+3 ----
    {
#pragma unroll
        for (int r = 0; r < 4; r++) {
            const int q = warp * 4 + r;
            float v[10];
#pragma unroll
            for (int c = 0; c < 10; c++) v[c] = Psh[q * PST + lane + 32 * c];

            float m = v[0];
#pragma unroll
            for (int c = 1; c < 10; c++) m = fmaxf(m, v[c]);
#pragma unroll
            for (int o = 16; o > 0; o >>= 1) m = fmaxf(m, __shfl_xor_sync(0xffffffffu, m, o));

            float e[10];
            float lsum = 0.f;
#pragma unroll
            for (int c = 0; c < 10; c++) { e[c] = __expf(v[c] - m); lsum += e[c]; }
#pragma unroll
            for (int o = 16; o > 0; o >>= 1) lsum += __shfl_xor_sync(0xffffffffu, lsum, o);
            const float inv = 1.f / lsum;

            float* prow = probs + ((size_t)bh * SEQ + (s0 + q)) * WIN;
#pragma unroll
            for (int c = 0; c < 10; c++) {
                const int col = lane + 32 * c;
                const float p = (v[c] > -1e8f) ? e[c] * inv : 0.f;
                Psh[q * PST + col] = p;
                const int oi = col - q;
                if (oi >= 0 && oi <= 256) prow[oi] = p;
            }
        }
    }
    __syncthreads();

    // ---- GEMM2: O[64 x 64] = P[64 x 320] * V[320 x 64], 4-way o-split ----
    // og = tid>>7 handles o in [og*80, og*80+80); 128 threads: tq (8) x td (16)
    // thread tile 8q x 4d
    {
        const int og = tid >> 7;           // 0..3
        const int t7 = tid & 127;
        const int tq = t7 & 7;             // rows tq + 8i
        const int td = t7 >> 3;            // cols td*4 .. +3
        float* Vsh = Ksh;

        float a0[8], a1[8], a2[8], a3[8];
#pragma unroll
        for (int i = 0; i < 8; i++) { a0[i]=0.f; a1[i]=0.f; a2[i]=0.f; a3[i]=0.f; }

        const int oend = og * 80 + 80;
#pragma unroll 2
        for (int oc = og * 80; oc < oend; oc += 4) {
            float4 Vv[4];
#pragma unroll
            for (int k = 0; k < 4; k++)
                Vv[k] = *(const float4*)(Vsh + (oc + k) * KST + td * 4);
#pragma unroll
            for (int i = 0; i < 8; i++) {
                const float4 Pv = *(const float4*)(Psh + (tq + 8 * i) * PST + oc);
                a0[i] += Pv.x * Vv[0].x; a0[i] += Pv.y * Vv[1].x;
                a0[i] += Pv.z * Vv[2].x; a0[i] += Pv.w * Vv[3].x;
                a1[i] += Pv.x * Vv[0].y; a1[i] += Pv.y * Vv[1].y;
                a1[i] += Pv.z * Vv[2].y; a1[i] += Pv.w * Vv[3].y;
                a2[i] += Pv.x * Vv[0].z; a2[i] += Pv.y * Vv[1].z;
                a2[i] += Pv.z * Vv[2].z; a2[i] += Pv.w * Vv[3].z;
                a3[i] += Pv.x * Vv[0].w; a3[i] += Pv.y * Vv[1].w;
                a3[i] += Pv.z * Vv[2].w; a3[i] += Pv.w * Vv[3].w;
            }
        }
        __syncthreads();   // all groups done reading Psh / Vsh

        // partial reduction through freed smem (overlay at sh base)
        if (og > 0) {
            float* scr = sh + (og - 1) * (64 * 68);
#pragma unroll
            for (int i = 0; i < 8; i++)
                *(float4*)(scr + (tq + 8 * i) * 68 + td * 4) =
                    make_float4(a0[i], a1[i], a2[i], a3[i]);
        }
        __syncthreads();

        if (og == 0) {
#pragma unroll
            for (int i = 0; i < 8; i++) {
                float4 r = make_float4(a0[i], a1[i], a2[i], a3[i]);
#pragma unroll
                for (int g = 0; g < 3; g++) {
                    const float4 p = *(const float4*)(sh + g * (64 * 68) + (tq + 8 * i) * 68 + td * 4);
                    r.x += p.x; r.y += p.y; r.z += p.z; r.w += p.w;
                }
                const int q = tq + 8 * i;
                float* orow = out + ((size_t)(s0 + q) * BATCH + b) * HID + head * HD;
                *(float4*)(orow + td * 4) = r;
            }
        }
    }
}

// ---------------- launch ------------------------------------------------------
extern "C" void kernel_launch(void* const* d_in, const int* in_sizes, int n_in,
                              void* d_out, int out_size)
{
    const float* q_in = (const float*)d_in[0];
    const float* k_in = (const float*)d_in[1];
    const float* v_in = (const float*)d_in[2];
    const unsigned char* mask = (const unsigned char*)d_in[3];
    const float* Wq = (const float*)d_in[4];
    const float* bq = (const float*)d_in[5];
    const float* Wk = (const float*)d_in[6];
    const float* bk = (const float*)d_in[7];
    const float* Wv = (const float*)d_in[8];
    const float* bv = (const float*)d_in[9];

    float* out   = (float*)d_out;
    float* probs = out + (size_t)SEQ * BATCH * HID;

    cudaFuncSetAttribute(attn_kernel, cudaFuncAttributeMaxDynamicSharedMemorySize,
                         ATT_SMEM_BYTES);

    dim3 g1(HID / BN, (SEQ * BATCH) / BM, 3);
    proj_kernel<<<g1, 256>>>(q_in, k_in, v_in, Wq, Wk, Wv, bq, bk, bv);

    dim3 g2(SEQ / TQ, BHD);
    attn_kernel<<<g2, 512, ATT_SMEM_BYTES>>>(mask, out, probs);
}

// round 4
// speedup vs baseline: 3.0144x; 2.4090x over previous
#include <cuda_runtime.h>
#include <cuda_bf16.h>
#include <math.h>
#include <stdint.h>

#define SEQ    4096
#define BATCH  4
#define HID    1024
#define NH     16
#define HD     64
#define BHD    (BATCH * NH)     // 64
#define WIN    257
#define HALF   128
#define MINSC  (-1e9f)
#define ROWS   (SEQ * BATCH)    // 16384

// ---------------- scratch (device globals; no allocation allowed) ------------
__device__ float g_q[(size_t)BHD * SEQ * HD];
__device__ float g_k[(size_t)BHD * SEQ * HD];
__device__ float g_v[(size_t)BHD * SEQ * HD];

__device__ __nv_bfloat16 g_xhi[3ull * ROWS * HID];
__device__ __nv_bfloat16 g_xlo[3ull * ROWS * HID];
__device__ __nv_bfloat16 g_whi[3ull * HID * HID];
__device__ __nv_bfloat16 g_wlo[3ull * HID * HID];

// ================= small PTX helpers ========================================
__device__ __forceinline__ uint32_t smem_u32(const void* p) {
    uint32_t a;
    asm("{ .reg .u64 t; cvta.to.shared.u64 t, %1; cvt.u32.u64 %0, t; }"
        : "=r"(a) : "l"(p));
    return a;
}
__device__ __forceinline__ void cp16(uint32_t s, const void* g) {
    asm volatile("cp.async.cg.shared.global [%0], [%1], 16;" :: "r"(s), "l"(g));
}
#define CP_COMMIT() asm volatile("cp.async.commit_group;" ::: "memory")
#define CP_WAIT1()  asm volatile("cp.async.wait_group 1;" ::: "memory")

__device__ __forceinline__ void ldm_x4(uint32_t* r, uint32_t addr) {
    asm volatile("ldmatrix.sync.aligned.m8n8.x4.shared.b16 {%0,%1,%2,%3}, [%4];"
        : "=r"(r[0]), "=r"(r[1]), "=r"(r[2]), "=r"(r[3]) : "r"(addr));
}
__device__ __forceinline__ void mma_bf16(float* c, const uint32_t* a,
                                         uint32_t b0, uint32_t b1) {
    asm volatile(
        "mma.sync.aligned.m16n8k16.row.col.f32.bf16.bf16.f32 "
        "{%0,%1,%2,%3}, {%4,%5,%6,%7}, {%8,%9}, {%0,%1,%2,%3};"
        : "+f"(c[0]), "+f"(c[1]), "+f"(c[2]), "+f"(c[3])
        : "r"(a[0]), "r"(a[1]), "r"(a[2]), "r"(a[3]), "r"(b0), "r"(b1));
}

// ================= conversion kernels =======================================
__global__ __launch_bounds__(256) void convert_x(
    const float* __restrict__ q, const float* __restrict__ k, const float* __restrict__ v)
{
    const int z = blockIdx.y;
    const float* src = (z == 0) ? q : (z == 1) ? k : v;
    const size_t i4 = (size_t)blockIdx.x * 256 + threadIdx.x;
    const float4 x = ((const float4*)src)[i4];
    __nv_bfloat16 h[4], l[4];
    const float f[4] = {x.x, x.y, x.z, x.w};
#pragma unroll
    for (int j = 0; j < 4; j++) {
        h[j] = __float2bfloat16(f[j]);
        l[j] = __float2bfloat16(f[j] - __bfloat162float(h[j]));
    }
    const size_t off = (size_t)z * ROWS * HID + i4 * 4;
    *(uint2*)(g_xhi + off) = *(const uint2*)h;
    *(uint2*)(g_xlo + off) = *(const uint2*)l;
}

__global__ __launch_bounds__(256) void convert_w(
    const float* __restrict__ wq, const float* __restrict__ wk, const float* __restrict__ wv)
{
    const int z = blockIdx.y;
    const float* src = (z == 0) ? wq : (z == 1) ? wk : wv;
    const size_t i4 = (size_t)blockIdx.x * 256 + threadIdx.x;
    const float4 x = ((const float4*)src)[i4];
    __nv_bfloat16 h[4], l[4];
    const float f[4] = {x.x, x.y, x.z, x.w};
#pragma unroll
    for (int j = 0; j < 4; j++) {
        h[j] = __float2bfloat16(f[j]);
        l[j] = __float2bfloat16(f[j] - __bfloat162float(h[j]));
    }
    const size_t off = (size_t)z * HID * HID + i4 * 4;
    *(uint2*)(g_whi + off) = *(const uint2*)h;
    *(uint2*)(g_wlo + off) = *(const uint2*)l;
}

// ================= mma.sync projection GEMM =================================
// C[r][h] = sum_j X[r][j] W[h][j] + b[h]; bf16x3 split.
// CTA: 128x128, BK=32. 8 warps = 2(m) x 4(n); warp tile 64x32.
// smem rows padded to 80 B (40 bf16) -> ldmatrix conflict-free.
#define PBM 128
#define PBN 128
#define PBK 32
#define RSTB 80                      // row stride bytes
#define TILEB (PBM * RSTB)           // 10240 per tile
#define STAGEB (4 * TILEB)           // AHI/ALO/BHI/BLO = 40960
#define PROJ_SMEM (2 * STAGEB)       // 81920

__global__ __launch_bounds__(256) void proj_mma_kernel(
    const float* __restrict__ bq, const float* __restrict__ bk, const float* __restrict__ bv)
{
    const int z   = blockIdx.z;
    const int bn0 = blockIdx.x * PBN;
    const int bm0 = blockIdx.y * PBM;
    const float* Bias = (z == 0) ? bq : (z == 1) ? bk : bv;
    float*       O    = (z == 0) ? g_q : (z == 1) ? g_k : g_v;
    const __nv_bfloat16* Xhi = g_xhi + (size_t)z * ROWS * HID;
    const __nv_bfloat16* Xlo = g_xlo + (size_t)z * ROWS * HID;
    const __nv_bfloat16* Whi = g_whi + (size_t)z * HID * HID;
    const __nv_bfloat16* Wlo = g_wlo + (size_t)z * HID * HID;

    extern __shared__ char smc[];
    const uint32_t sb = smem_u32(smc);

    const int tid  = threadIdx.x;
    const int warp = tid >> 5;
    const int lane = tid & 31;
    const int mw   = warp >> 2;       // 0..1 -> m offset mw*64
    const int nw   = warp & 3;        // 0..3 -> n offset nw*32

    // ---- async stage loader: 2048 x 16B per stage, 8 per thread ----
    auto load_stage = [&](int st, int k0) {
        const uint32_t base = sb + st * STAGEB;
        const __nv_bfloat16* srcs[4] = {Xhi, Xlo, Whi, Wlo};
        const int rb[4] = {bm0, bm0, bn0, bn0};
#pragma unroll
        for (int t = 0; t < 4; t++) {
#pragma unroll
            for (int i = 0; i < 2; i++) {
                const int idx = tid + 256 * i;       // 0..511
                const int row = idx >> 2;
                const int g   = idx & 3;
                const __nv_bfloat16* gp =
                    srcs[t] + (size_t)(rb[t] + row) * HID + k0 + g * 8;
                cp16(base + t * TILEB + row * RSTB + g * 16, gp);
            }
        }
    };

    float c[4][4][4];
#pragma unroll
    for (int i = 0; i < 4; i++)
#pragma unroll
        for (int j = 0; j < 4; j++)
#pragma unroll
            for (int e = 0; e < 4; e++) c[i][j][e] = 0.f;

    load_stage(0, 0);
    CP_COMMIT();

    // fragment address components (per-lane, loop-invariant)
    const uint32_t a_row  = mw * 64 + (lane & 15);
    const uint32_t a_gsel = (lane >> 4);            // 0/1
    const uint32_t b_rgrp = lane >> 3;              // 0..3
    const uint32_t b_row  = nw * 32 + ((b_rgrp >> 1) << 3) + (lane & 7);
    const uint32_t b_gsel = (b_rgrp & 1);

    for (int kt = 0; kt < HID / PBK; kt++) {
        if (kt + 1 < HID / PBK) load_stage((kt + 1) & 1, (kt + 1) * PBK);
        CP_COMMIT();
        CP_WAIT1();
        __syncthreads();

        const uint32_t stb = sb + (kt & 1) * STAGEB;
        const uint32_t Ah_b = stb;
        const uint32_t Al_b = stb + TILEB;
        const uint32_t Bh_b = stb + 2 * TILEB;
        const uint32_t Bl_b = stb + 3 * TILEB;

#pragma unroll
        for (int ks = 0; ks < 2; ks++) {
            // B hi: 2 x ldmatrix.x4 -> 4 n-tiles x {b0,b1}
            uint32_t Bh[4][2];
#pragma unroll
            for (int jp = 0; jp < 2; jp++) {
                uint32_t r[4];
                ldm_x4(r, Bh_b + (b_row + jp * 16) * RSTB + (ks * 2 + b_gsel) * 16);
                Bh[jp * 2 + 0][0] = r[0]; Bh[jp * 2 + 0][1] = r[1];
                Bh[jp * 2 + 1][0] = r[2]; Bh[jp * 2 + 1][1] = r[3];
            }
            // A hi: 4 x ldmatrix.x4
            uint32_t Ah[4][4];
#pragma unroll
            for (int i = 0; i < 4; i++)
                ldm_x4(Ah[i], Ah_b + (a_row + i * 16) * RSTB + (ks * 2 + a_gsel) * 16);
            // hi * hi
#pragma unroll
            for (int i = 0; i < 4; i++)
#pragma unroll
                for (int j = 0; j < 4; j++)
                    mma_bf16(c[i][j], Ah[i], Bh[j][0], Bh[j][1]);
            // lo * hi
            {
                uint32_t Al[4][4];
#pragma unroll
                for (int i = 0; i < 4; i++)
                    ldm_x4(Al[i], Al_b + (a_row + i * 16) * RSTB + (ks * 2 + a_gsel) * 16);
#pragma unroll
                for (int i = 0; i < 4; i++)
#pragma unroll
                    for (int j = 0; j < 4; j++)
                        mma_bf16(c[i][j], Al[i], Bh[j][0], Bh[j][1]);
            }
            // hi * lo
            {
                uint32_t Bl[4][2];
#pragma unroll
                for (int jp = 0; jp < 2; jp++) {
                    uint32_t r[4];
                    ldm_x4(r, Bl_b + (b_row + jp * 16) * RSTB + (ks * 2 + b_gsel) * 16);
                    Bl[jp * 2 + 0][0] = r[0]; Bl[jp * 2 + 0][1] = r[1];
                    Bl[jp * 2 + 1][0] = r[2]; Bl[jp * 2 + 1][1] = r[3];
                }
#pragma unroll
                for (int i = 0; i < 4; i++)
#pragma unroll
                    for (int j = 0; j < 4; j++)
                        mma_bf16(c[i][j], Ah[i], Bl[j][0], Bl[j][1]);
            }
        }
        __syncthreads();
    }

    // ---- epilogue: bias add + scatter into head-split layout ----
    const int l4 = lane >> 2, lm = lane & 3;
#pragma unroll
    for (int j = 0; j < 4; j++) {
        const int h    = bn0 + nw * 32 + j * 8 + lm * 2;
        const int head = h >> 6;
        const int d    = h & 63;
        const float bi0 = Bias[h], bi1 = Bias[h + 1];
#pragma unroll
        for (int i = 0; i < 4; i++) {
            const int r0 = bm0 + mw * 64 + i * 16 + l4;
            const int r1 = r0 + 8;
            const int s0r = r0 >> 2, b0r = r0 & 3;
            const int s1r = r1 >> 2, b1r = r1 & 3;
            *(float2*)(O + ((size_t)(b0r * NH + head) * SEQ + s0r) * HD + d) =
                make_float2(c[i][j][0] + bi0, c[i][j][1] + bi1);
            *(float2*)(O + ((size_t)(b1r * NH + head) * SEQ + s1r) * HD + d) =
                make_float2(c[i][j][2] + bi0, c[i][j][3] + bi1);
        }
    }
}

// ---------------- local attention (unchanged from round 2) ------------------
#define TQ   64
#define WR   320
#define KST  68
#define QST  68
#define PST  324
#define NFL  (WR * KST + TQ * QST + TQ * PST + 128)
#define ATT_SMEM_BYTES (NFL * 4)

__global__ __launch_bounds__(512) void attn_kernel(
    const unsigned char* __restrict__ mask,
    float* __restrict__ out, float* __restrict__ probs)
{
    const int bh   = blockIdx.y;
    const int s0   = blockIdx.x * TQ;
    const int b    = bh >> 4;
    const int head = bh & 15;
    const int base = s0 - HALF;

    const float* Kp = g_k + (size_t)bh * SEQ * HD;
    const float* Vp = g_v + (size_t)bh * SEQ * HD;
    const float* Qp = g_q + (size_t)bh * SEQ * HD;

    extern __shared__ float sh[];
    float* Ksh = sh;
    float* Qsh = Ksh + WR * KST;
    float* Psh = Qsh + TQ * QST;
    unsigned char* msh = (unsigned char*)(Psh + TQ * PST);

    const int tid = threadIdx.x;

    for (int o = tid; o < WR; o += 512) {
        const int t = base + o;
        msh[o] = (t >= 0 && t < SEQ && mask[t * BATCH + b] == 0) ? 1 : 0;
    }
    for (int idx = tid; idx < WR * 16; idx += 512) {
        const int row = idx >> 4;
        const int c4  = (idx & 15) * 4;
        const int t   = base + row;
        float4 kv = make_float4(0.f, 0.f, 0.f, 0.f);
        if (t >= 0 && t < SEQ) kv = *(const float4*)(Kp + (size_t)t * HD + c4);
        *(float4*)(Ksh + row * KST + c4) = kv;
    }
    for (int idx = tid; idx < TQ * 16; idx += 512) {
        const int row = idx >> 4;
        const int c4  = (idx & 15) * 4;
        *(float4*)(Qsh + row * QST + c4) =
            *(const float4*)(Qp + (size_t)(s0 + row) * HD + c4);
    }
    __syncthreads();

    const int warp = tid >> 5;
    const int lane = tid & 31;

    {
        const int wq = warp >> 3;
        const int wo = warp & 7;
        const int lq = lane & 3;
        const int lo = lane >> 2;
        const int qb = wq * 32 + lq;
        const int ob = wo * 40 + lo;

        float acc[8][5];
#pragma unroll
        for (int i = 0; i < 8; i++)
#pragma unroll
            for (int j = 0; j < 5; j++) acc[i][j] = 0.f;

#pragma unroll 2
        for (int dc = 0; dc < 16; dc++) {
            const int d = dc * 4;
            float4 Qv[8], Kv[5];
#pragma unroll
            for (int i = 0; i < 8; i++)
                Qv[i] = *(const float4*)(Qsh + (qb + 4 * i) * QST + d);
#pragma unroll
            for (int j = 0; j < 5; j++)
                Kv[j] = *(const float4*)(Ksh + (ob + 8 * j) * KST + d);
#pragma unroll
            for (int i = 0; i < 8; i++)
#pragma unroll
                for (int j = 0; j < 5; j++) {
                    acc[i][j] += Qv[i].x * Kv[j].x;
                    acc[i][j] += Qv[i].y * Kv[j].y;
                    acc[i][j] += Qv[i].z * Kv[j].z;
                    acc[i][j] += Qv[i].w * Kv[j].w;
                }
        }

#pragma unroll
        for (int i = 0; i < 8; i++) {
            const int q = qb + 4 * i;
#pragma unroll
            for (int j = 0; j < 5; j++) {
                const int o = ob + 8 * j;
                float s;
                if (o < q || o > q + 256)      s = -1e30f;
                else if (!msh[o])              s = MINSC;
                else                           s = acc[i][j];
                Psh[q * PST + o] = s;
            }
        }
    }
    __syncthreads();

    for (int idx = tid; idx < WR * 16; idx += 512) {
        const int row = idx >> 4;
        const int c4  = (idx & 15) * 4;
        const int t   = base + row;
        float4 vv = make_float4(0.f, 0.f, 0.f, 0.f);
        if (t >= 0 && t < SEQ) vv = *(const float4*)(Vp + (size_t)t * HD + c4);
        *(float4*)(Ksh + row * KST + c4) = vv;
    }

    {
#pragma unroll
        for (int r = 0; r < 4; r++) {
            const int q = warp * 4 + r;
            float v[10];
#pragma unroll
            for (int c = 0; c < 10; c++) v[c] = Psh[q * PST + lane + 32 * c];

            float m = v[0];
#pragma unroll
            for (int c = 1; c < 10; c++) m = fmaxf(m, v[c]);
#pragma unroll
            for (int o = 16; o > 0; o >>= 1) m = fmaxf(m, __shfl_xor_sync(0xffffffffu, m, o));

            float e[10];
            float lsum = 0.f;
#pragma unroll
            for (int c = 0; c < 10; c++) { e[c] = __expf(v[c] - m); lsum += e[c]; }
#pragma unroll
            for (int o = 16; o > 0; o >>= 1) lsum += __shfl_xor_sync(0xffffffffu, lsum, o);
            const float inv = 1.f / lsum;

            float* prow = probs + ((size_t)bh * SEQ + (s0 + q)) * WIN;
#pragma unroll
            for (int c = 0; c < 10; c++) {
                const int col = lane + 32 * c;
                const float p = (v[c] > -1e8f) ? e[c] * inv : 0.f;
                Psh[q * PST + col] = p;
                const int oi = col - q;
                if (oi >= 0 && oi <= 256) prow[oi] = p;
            }
        }
    }
    __syncthreads();

    {
        const int og = tid >> 7;
        const int t7 = tid & 127;
        const int tq = t7 & 7;
        const int td = t7 >> 3;
        float* Vsh = Ksh;

        float a0[8], a1[8], a2[8], a3[8];
#pragma unroll
        for (int i = 0; i < 8; i++) { a0[i]=0.f; a1[i]=0.f; a2[i]=0.f; a3[i]=0.f; }

        const int oend = og * 80 + 80;
#pragma unroll 2
        for (int oc = og * 80; oc < oend; oc += 4) {
            float4 Vv[4];
#pragma unroll
            for (int k = 0; k < 4; k++)
                Vv[k] = *(const float4*)(Vsh + (oc + k) * KST + td * 4);
#pragma unroll
            for (int i = 0; i < 8; i++) {
                const float4 Pv = *(const float4*)(Psh + (tq + 8 * i) * PST + oc);
                a0[i] += Pv.x * Vv[0].x; a0[i] += Pv.y * Vv[1].x;
                a0[i] += Pv.z * Vv[2].x; a0[i] += Pv.w * Vv[3].x;
                a1[i] += Pv.x * Vv[0].y; a1[i] += Pv.y * Vv[1].y;
                a1[i] += Pv.z * Vv[2].y; a1[i] += Pv.w * Vv[3].y;
                a2[i] += Pv.x * Vv[0].z; a2[i] += Pv.y * Vv[1].z;
                a2[i] += Pv.z * Vv[2].z; a2[i] += Pv.w * Vv[3].z;
                a3[i] += Pv.x * Vv[0].w; a3[i] += Pv.y * Vv[1].w;
                a3[i] += Pv.z * Vv[2].w; a3[i] += Pv.w * Vv[3].w;
            }
        }
        __syncthreads();

        if (og > 0) {
            float* scr = sh + (og - 1) * (64 * 68);
#pragma unroll
            for (int i = 0; i < 8; i++)
                *(float4*)(scr + (tq + 8 * i) * 68 + td * 4) =
                    make_float4(a0[i], a1[i], a2[i], a3[i]);
        }
        __syncthreads();

        if (og == 0) {
#pragma unroll
            for (int i = 0; i < 8; i++) {
                float4 r = make_float4(a0[i], a1[i], a2[i], a3[i]);
#pragma unroll
                for (int g = 0; g < 3; g++) {
                    const float4 p = *(const float4*)(sh + g * (64 * 68) + (tq + 8 * i) * 68 + td * 4);
                    r.x += p.x; r.y += p.y; r.z += p.z; r.w += p.w;
                }
                const int q = tq + 8 * i;
                float* orow = out + ((size_t)(s0 + q) * BATCH + b) * HID + head * HD;
                *(float4*)(orow + td * 4) = r;
            }
        }
    }
}

// ---------------- launch ------------------------------------------------------
extern "C" void kernel_launch(void* const* d_in, const int* in_sizes, int n_in,
                              void* d_out, int out_size)
{
    const float* q_in = (const float*)d_in[0];
    const float* k_in = (const float*)d_in[1];
    const float* v_in = (const float*)d_in[2];
    const unsigned char* mask = (const unsigned char*)d_in[3];
    const float* Wq = (const float*)d_in[4];
    const float* bq = (const float*)d_in[5];
    const float* Wk = (const float*)d_in[6];
    const float* bk = (const float*)d_in[7];
    const float* Wv = (const float*)d_in[8];
    const float* bv = (const float*)d_in[9];

    float* out   = (float*)d_out;
    float* probs = out + (size_t)SEQ * BATCH * HID;

    cudaFuncSetAttribute(proj_mma_kernel, cudaFuncAttributeMaxDynamicSharedMemorySize,
                         PROJ_SMEM);
    cudaFuncSetAttribute(attn_kernel, cudaFuncAttributeMaxDynamicSharedMemorySize,
                         ATT_SMEM_BYTES);

    dim3 gx(ROWS * HID / 4 / 256, 3);
    convert_x<<<gx, 256>>>(q_in, k_in, v_in);
    dim3 gw(HID * HID / 4 / 256, 3);
    convert_w<<<gw, 256>>>(Wq, Wk, Wv);

    dim3 gp(HID / PBN, ROWS / PBM, 3);
    proj_mma_kernel<<<gp, 256, PROJ_SMEM>>>(bq, bk, bv);

    dim3 ga(SEQ / TQ, BHD);
    attn_kernel<<<ga, 512, ATT_SMEM_BYTES>>>(mask, out, probs);
}

// round 5
// speedup vs baseline: 3.3244x; 1.1028x over previous
#include <cuda_runtime.h>
#include <cuda_bf16.h>
#include <math.h>
#include <stdint.h>

#define SEQ    4096
#define BATCH  4
#define HID    1024
#define NH     16
#define HD     64
#define BHD    (BATCH * NH)     // 64
#define WIN    257
#define HALF   128
#define MINSC  (-1e9f)
#define ROWS   (SEQ * BATCH)    // 16384

// ---------------- scratch (device globals; no allocation allowed) ------------
// projected q/k/v in bf16 hi/lo split, head-split layout [z][bh][s][d]
__device__ __nv_bfloat16 g_ph[3ull * BHD * SEQ * HD];
__device__ __nv_bfloat16 g_pl[3ull * BHD * SEQ * HD];

__device__ __nv_bfloat16 g_xhi[3ull * ROWS * HID];
__device__ __nv_bfloat16 g_xlo[3ull * ROWS * HID];
__device__ __nv_bfloat16 g_whi[3ull * HID * HID];
__device__ __nv_bfloat16 g_wlo[3ull * HID * HID];

// ================= small PTX helpers ========================================
__device__ __forceinline__ uint32_t smem_u32(const void* p) {
    uint32_t a;
    asm("{ .reg .u64 t; cvta.to.shared.u64 t, %1; cvt.u32.u64 %0, t; }"
        : "=r"(a) : "l"(p));
    return a;
}
__device__ __forceinline__ void cp16(uint32_t s, const void* g) {
    asm volatile("cp.async.cg.shared.global [%0], [%1], 16;" :: "r"(s), "l"(g));
}
__device__ __forceinline__ void cp16z(uint32_t s, const void* g, int sz) {
    asm volatile("cp.async.cg.shared.global [%0], [%1], 16, %2;"
                 :: "r"(s), "l"(g), "r"(sz));
}
#define CP_COMMIT() asm volatile("cp.async.commit_group;" ::: "memory")
#define CP_WAIT1()  asm volatile("cp.async.wait_group 1;" ::: "memory")
#define CP_WAIT0()  asm volatile("cp.async.wait_group 0;" ::: "memory")

__device__ __forceinline__ void ldm_x4(uint32_t* r, uint32_t addr) {
    asm volatile("ldmatrix.sync.aligned.m8n8.x4.shared.b16 {%0,%1,%2,%3}, [%4];"
        : "=r"(r[0]), "=r"(r[1]), "=r"(r[2]), "=r"(r[3]) : "r"(addr));
}
__device__ __forceinline__ void ldm_x4_t(uint32_t* r, uint32_t addr) {
    asm volatile("ldmatrix.sync.aligned.m8n8.x4.trans.shared.b16 {%0,%1,%2,%3}, [%4];"
        : "=r"(r[0]), "=r"(r[1]), "=r"(r[2]), "=r"(r[3]) : "r"(addr));
}
__device__ __forceinline__ void mma_bf16(float* c, const uint32_t* a,
                                         uint32_t b0, uint32_t b1) {
    asm volatile(
        "mma.sync.aligned.m16n8k16.row.col.f32.bf16.bf16.f32 "
        "{%0,%1,%2,%3}, {%4,%5,%6,%7}, {%8,%9}, {%0,%1,%2,%3};"
        : "+f"(c[0]), "+f"(c[1]), "+f"(c[2]), "+f"(c[3])
        : "r"(a[0]), "r"(a[1]), "r"(a[2]), "r"(a[3]), "r"(b0), "r"(b1));
}

// ================= conversion kernels =======================================
__global__ __launch_bounds__(256) void convert_x(
    const float* __restrict__ q, const float* __restrict__ k, const float* __restrict__ v)
{
    const int z = blockIdx.y;
    const float* src = (z == 0) ? q : (z == 1) ? k : v;
    const size_t i4 = (size_t)blockIdx.x * 256 + threadIdx.x;
    const float4 x = ((const float4*)src)[i4];
    __nv_bfloat16 h[4], l[4];
    const float f[4] = {x.x, x.y, x.z, x.w};
#pragma unroll
    for (int j = 0; j < 4; j++) {
        h[j] = __float2bfloat16(f[j]);
        l[j] = __float2bfloat16(f[j] - __bfloat162float(h[j]));
    }
    const size_t off = (size_t)z * ROWS * HID + i4 * 4;
    *(uint2*)(g_xhi + off) = *(const uint2*)h;
    *(uint2*)(g_xlo + off) = *(const uint2*)l;
}

__global__ __launch_bounds__(256) void convert_w(
    const float* __restrict__ wq, const float* __restrict__ wk, const float* __restrict__ wv)
{
    const int z = blockIdx.y;
    const float* src = (z == 0) ? wq : (z == 1) ? wk : wv;
    const size_t i4 = (size_t)blockIdx.x * 256 + threadIdx.x;
    const float4 x = ((const float4*)src)[i4];
    __nv_bfloat16 h[4], l[4];
    const float f[4] = {x.x, x.y, x.z, x.w};
#pragma unroll
    for (int j = 0; j < 4; j++) {
        h[j] = __float2bfloat16(f[j]);
        l[j] = __float2bfloat16(f[j] - __bfloat162float(h[j]));
    }
    const size_t off = (size_t)z * HID * HID + i4 * 4;
    *(uint2*)(g_whi + off) = *(const uint2*)h;
    *(uint2*)(g_wlo + off) = *(const uint2*)l;
}

// ================= mma.sync projection GEMM =================================
#define PBM 128
#define PBN 128
#define PBK 32
#define RSTB 80
#define TILEB (PBM * RSTB)
#define STAGEB (4 * TILEB)
#define PROJ_SMEM (2 * STAGEB)

__global__ __launch_bounds__(256) void proj_mma_kernel(
    const float* __restrict__ bq, const float* __restrict__ bk, const float* __restrict__ bv)
{
    const int z   = blockIdx.z;
    const int bn0 = blockIdx.x * PBN;
    const int bm0 = blockIdx.y * PBM;
    const float* Bias = (z == 0) ? bq : (z == 1) ? bk : bv;
    const size_t zoff = (size_t)z * BHD * SEQ * HD;
    const __nv_bfloat16* Xhi = g_xhi + (size_t)z * ROWS * HID;
    const __nv_bfloat16* Xlo = g_xlo + (size_t)z * ROWS * HID;
    const __nv_bfloat16* Whi = g_whi + (size_t)z * HID * HID;
    const __nv_bfloat16* Wlo = g_wlo + (size_t)z * HID * HID;

    extern __shared__ char smc[];
    const uint32_t sb = smem_u32(smc);

    const int tid  = threadIdx.x;
    const int warp = tid >> 5;
    const int lane = tid & 31;
    const int mw   = warp >> 2;
    const int nw   = warp & 3;

    auto load_stage = [&](int st, int k0) {
        const uint32_t base = sb + st * STAGEB;
        const __nv_bfloat16* srcs[4] = {Xhi, Xlo, Whi, Wlo};
        const int rb[4] = {bm0, bm0, bn0, bn0};
#pragma unroll
        for (int t = 0; t < 4; t++) {
#pragma unroll
            for (int i = 0; i < 2; i++) {
                const int idx = tid + 256 * i;
                const int row = idx >> 2;
                const int g   = idx & 3;
                const __nv_bfloat16* gp =
                    srcs[t] + (size_t)(rb[t] + row) * HID + k0 + g * 8;
                cp16(base + t * TILEB + row * RSTB + g * 16, gp);
            }
        }
    };

    float c[4][4][4];
#pragma unroll
    for (int i = 0; i < 4; i++)
#pragma unroll
        for (int j = 0; j < 4; j++)
#pragma unroll
            for (int e = 0; e < 4; e++) c[i][j][e] = 0.f;

    load_stage(0, 0);
    CP_COMMIT();

    const uint32_t a_row  = mw * 64 + (lane & 15);
    const uint32_t a_gsel = (lane >> 4);
    const uint32_t b_rgrp = lane >> 3;
    const uint32_t b_row  = nw * 32 + ((b_rgrp >> 1) << 3) + (lane & 7);
    const uint32_t b_gsel = (b_rgrp & 1);

    for (int kt = 0; kt < HID / PBK; kt++) {
        if (kt + 1 < HID / PBK) load_stage((kt + 1) & 1, (kt + 1) * PBK);
        CP_COMMIT();
        CP_WAIT1();
        __syncthreads();

        const uint32_t stb = sb + (kt & 1) * STAGEB;
        const uint32_t Ah_b = stb;
        const uint32_t Al_b = stb + TILEB;
        const uint32_t Bh_b = stb + 2 * TILEB;
        const uint32_t Bl_b = stb + 3 * TILEB;

#pragma unroll
        for (int ks = 0; ks < 2; ks++) {
            uint32_t Bh[4][2];
#pragma unroll
            for (int jp = 0; jp < 2; jp++) {
                uint32_t r[4];
                ldm_x4(r, Bh_b + (b_row + jp * 16) * RSTB + (ks * 2 + b_gsel) * 16);
                Bh[jp * 2 + 0][0] = r[0]; Bh[jp * 2 + 0][1] = r[1];
                Bh[jp * 2 + 1][0] = r[2]; Bh[jp * 2 + 1][1] = r[3];
            }
            uint32_t Ah[4][4];
#pragma unroll
            for (int i = 0; i < 4; i++)
                ldm_x4(Ah[i], Ah_b + (a_row + i * 16) * RSTB + (ks * 2 + a_gsel) * 16);
#pragma unroll
            for (int i = 0; i < 4; i++)
#pragma unroll
                for (int j = 0; j < 4; j++)
                    mma_bf16(c[i][j], Ah[i], Bh[j][0], Bh[j][1]);
            {
                uint32_t Al[4][4];
#pragma unroll
                for (int i = 0; i < 4; i++)
                    ldm_x4(Al[i], Al_b + (a_row + i * 16) * RSTB + (ks * 2 + a_gsel) * 16);
#pragma unroll
                for (int i = 0; i < 4; i++)
#pragma unroll
                    for (int j = 0; j < 4; j++)
                        mma_bf16(c[i][j], Al[i], Bh[j][0], Bh[j][1]);
            }
            {
                uint32_t Bl[4][2];
#pragma unroll
                for (int jp = 0; jp < 2; jp++) {
                    uint32_t r[4];
                    ldm_x4(r, Bl_b + (b_row + jp * 16) * RSTB + (ks * 2 + b_gsel) * 16);
                    Bl[jp * 2 + 0][0] = r[0]; Bl[jp * 2 + 0][1] = r[1];
                    Bl[jp * 2 + 1][0] = r[2]; Bl[jp * 2 + 1][1] = r[3];
                }
#pragma unroll
                for (int i = 0; i < 4; i++)
#pragma unroll
                    for (int j = 0; j < 4; j++)
                        mma_bf16(c[i][j], Ah[i], Bl[j][0], Bl[j][1]);
            }
        }
        __syncthreads();
    }

    // ---- epilogue: bias add, split to bf16 hi/lo, head-split scatter ----
    const int l4 = lane >> 2, lm = lane & 3;
#pragma unroll
    for (int j = 0; j < 4; j++) {
        const int h    = bn0 + nw * 32 + j * 8 + lm * 2;
        const int head = h >> 6;
        const int d    = h & 63;
        const float bi0 = Bias[h], bi1 = Bias[h + 1];
#pragma unroll
        for (int i = 0; i < 4; i++) {
            const int r0 = bm0 + mw * 64 + i * 16 + l4;
            const int r1 = r0 + 8;
#pragma unroll
            for (int half = 0; half < 2; half++) {
                const int rr = half ? r1 : r0;
                const float v0 = c[i][j][half * 2 + 0] + bi0;
                const float v1 = c[i][j][half * 2 + 1] + bi1;
                __nv_bfloat162 hh, ll;
                hh.x = __float2bfloat16(v0);
                hh.y = __float2bfloat16(v1);
                ll.x = __float2bfloat16(v0 - __bfloat162float(hh.x));
                ll.y = __float2bfloat16(v1 - __bfloat162float(hh.y));
                const int sr = rr >> 2, br = rr & 3;
                const size_t o = zoff + ((size_t)(br * NH + head) * SEQ + sr) * HD + d;
                *(__nv_bfloat162*)(g_ph + o) = hh;
                *(__nv_bfloat162*)(g_pl + o) = ll;
            }
        }
    }
}

// ================= tensor-core local attention ==============================
// 256 threads. GEMM1: 8 warps = 2(m) x 4(n), warp tile 32q x 80key.
// GEMM2: 8 warps = 4(m) x 2(n), warp tile 16q x 32dim.
#define TQ   64
#define WR   320
#define KSTB 144                 // K/V row stride bytes (72 bf16)
#define PSTB 656                 // P row stride bytes (328 bf16)

#define S_KH   0
#define S_KL   46080
#define S_QH   92160
#define S_QL   101376
#define S_PH   110592
#define S_PL   152576
#define S_MSK  194560
#define S_RMAX 194944
#define S_RSUM 195968
#define ATT_SMEM 197120

__global__ __launch_bounds__(256) void attn_kernel(
    const unsigned char* __restrict__ mask,
    float* __restrict__ out, float* __restrict__ probs)
{
    const int bh   = blockIdx.y;
    const int s0   = blockIdx.x * TQ;
    const int b    = bh >> 4;
    const int head = bh & 15;
    const int base = s0 - HALF;

    const __nv_bfloat16* Qh = g_ph + (size_t)(0 * BHD + bh) * SEQ * HD;
    const __nv_bfloat16* Ql = g_pl + (size_t)(0 * BHD + bh) * SEQ * HD;
    const __nv_bfloat16* Kh = g_ph + (size_t)(1 * BHD + bh) * SEQ * HD;
    const __nv_bfloat16* Kl = g_pl + (size_t)(1 * BHD + bh) * SEQ * HD;
    const __nv_bfloat16* Vh = g_ph + (size_t)(2 * BHD + bh) * SEQ * HD;
    const __nv_bfloat16* Vl = g_pl + (size_t)(2 * BHD + bh) * SEQ * HD;

    extern __shared__ char smc[];
    const uint32_t sb = smem_u32(smc);
    unsigned char* msh = (unsigned char*)(smc + S_MSK);

    const int tid  = threadIdx.x;
    const int warp = tid >> 5;
    const int lane = tid & 31;
    const int lane4 = lane >> 2, lanem = lane & 3;

    // ---- stage 1: mask + K hi/lo + Q hi/lo ----
    for (int o = tid; o < WR; o += 256) {
        const int t = base + o;
        msh[o] = (t >= 0 && t < SEQ && mask[t * BATCH + b] == 0) ? 1 : 0;
    }
#pragma unroll
    for (int it = 0; it < 10; it++) {
        const int idx = tid + 256 * it;          // < 2560
        const int row = idx >> 3, g = idx & 7;
        const int t = base + row;
        const int ok = (t >= 0 && t < SEQ);
        const int tc = ok ? t : 0;
        const int sz = ok ? 16 : 0;
        cp16z(sb + S_KH + row * KSTB + g * 16, Kh + (size_t)tc * HD + g * 8, sz);
        cp16z(sb + S_KL + row * KSTB + g * 16, Kl + (size_t)tc * HD + g * 8, sz);
    }
#pragma unroll
    for (int it = 0; it < 2; it++) {
        const int idx = tid + 256 * it;          // < 512
        const int row = idx >> 3, g = idx & 7;
        cp16(sb + S_QH + row * KSTB + g * 16, Qh + (size_t)(s0 + row) * HD + g * 8);
        cp16(sb + S_QL + row * KSTB + g * 16, Ql + (size_t)(s0 + row) * HD + g * 8);
    }
    CP_COMMIT();
    CP_WAIT0();
    __syncthreads();

    // ---- GEMM1: S = Q K^T (bf16x3) ----
    const int mw = warp >> 2;        // 0..1
    const int nw = warp & 3;         // 0..3
    const uint32_t a_off = (uint32_t)(lane & 15) * KSTB + (uint32_t)(lane >> 4) * 16;
    const uint32_t b_off = (uint32_t)((((lane >> 4) & 1) << 3) + (lane & 7)) * KSTB
                         + (uint32_t)((lane >> 3) & 1) * 16;

    float c1[2][10][4];
#pragma unroll
    for (int i = 0; i < 2; i++)
#pragma unroll
        for (int j = 0; j < 10; j++)
#pragma unroll
            for (int e = 0; e < 4; e++) c1[i][j][e] = 0.f;

#pragma unroll
    for (int kt = 0; kt < 4; kt++) {
        uint32_t Ah[2][4], Al[2][4];
#pragma unroll
        for (int mt = 0; mt < 2; mt++) {
            const uint32_t qa = sb + S_QH + (uint32_t)(mw * 32 + mt * 16) * KSTB
                              + a_off + kt * 32;
            ldm_x4(Ah[mt], qa);
            ldm_x4(Al[mt], qa + (S_QL - S_QH));
        }
#pragma unroll
        for (int np = 0; np < 5; np++) {
            const uint32_t ka = sb + S_KH + (uint32_t)(nw * 80 + np * 16) * KSTB
                              + b_off + kt * 32;
            uint32_t rh[4], rl[4];
            ldm_x4(rh, ka);
            ldm_x4(rl, ka + (S_KL - S_KH));
#pragma unroll
            for (int j = 0; j < 2; j++) {
                const int nt = np * 2 + j;
                const uint32_t bh0 = rh[2 * j], bh1 = rh[2 * j + 1];
                const uint32_t bl0 = rl[2 * j], bl1 = rl[2 * j + 1];
                mma_bf16(c1[0][nt], Ah[0], bh0, bh1);
                mma_bf16(c1[1][nt], Ah[1], bh0, bh1);
                mma_bf16(c1[0][nt], Al[0], bh0, bh1);
                mma_bf16(c1[1][nt], Al[1], bh0, bh1);
                mma_bf16(c1[0][nt], Ah[0], bl0, bl1);
                mma_bf16(c1[1][nt], Ah[1], bl0, bl1);
            }
        }
    }
    __syncthreads();   // done reading K smem

    // ---- overlap: stage V hi/lo into the K buffers ----
#pragma unroll
    for (int it = 0; it < 10; it++) {
        const int idx = tid + 256 * it;
        const int row = idx >> 3, g = idx & 7;
        const int t = base + row;
        const int ok = (t >= 0 && t < SEQ);
        const int tc = ok ? t : 0;
        const int sz = ok ? 16 : 0;
        cp16z(sb + S_KH + row * KSTB + g * 16, Vh + (size_t)tc * HD + g * 8, sz);
        cp16z(sb + S_KL + row * KSTB + g * 16, Vl + (size_t)tc * HD + g * 8, sz);
    }
    CP_COMMIT();

    // ---- band/mask epilogue on fragments ----
    const int r0w = mw * 32 + lane4;
    const int c0w = nw * 80 + 2 * lanem;
    uint32_t vb[2][2] = {{0u, 0u}, {0u, 0u}};
#pragma unroll
    for (int mt = 0; mt < 2; mt++)
#pragma unroll
        for (int nt = 0; nt < 10; nt++)
#pragma unroll
            for (int e = 0; e < 4; e++) {
                const int eh = e >> 1, el = e & 1;
                const int r = r0w + mt * 16 + eh * 8;
                const int cc = c0w + nt * 8 + el;
                float s = c1[mt][nt][e];
                const bool inband = (cc >= r) && (cc <= r + 256);
                const bool valid  = inband && msh[cc];
                if (!inband)      s = -1e30f;
                else if (!valid)  s = MINSC;
                c1[mt][nt][e] = s;
                if (valid) vb[mt][eh] |= 1u << (nt * 2 + el);
            }

    // ---- softmax: row max ----
    float pm[2][2] = {{-3e38f, -3e38f}, {-3e38f, -3e38f}};
#pragma unroll
    for (int mt = 0; mt < 2; mt++)
#pragma unroll
        for (int nt = 0; nt < 10; nt++)
#pragma unroll
            for (int e = 0; e < 4; e++)
                pm[mt][e >> 1] = fmaxf(pm[mt][e >> 1], c1[mt][nt][e]);
#pragma unroll
    for (int mt = 0; mt < 2; mt++)
#pragma unroll
        for (int eh = 0; eh < 2; eh++) {
            pm[mt][eh] = fmaxf(pm[mt][eh], __shfl_xor_sync(0xffffffffu, pm[mt][eh], 1));
            pm[mt][eh] = fmaxf(pm[mt][eh], __shfl_xor_sync(0xffffffffu, pm[mt][eh], 2));
        }
    if (lanem == 0) {
#pragma unroll
        for (int mt = 0; mt < 2; mt++)
#pragma unroll
            for (int eh = 0; eh < 2; eh++) {
                const int r = r0w + mt * 16 + eh * 8;
                *(float*)(smc + S_RMAX + (r * 4 + nw) * 4) = pm[mt][eh];
            }
    }
    __syncthreads();
    float M[2][2];
#pragma unroll
    for (int mt = 0; mt < 2; mt++)
#pragma unroll
        for (int eh = 0; eh < 2; eh++) {
            const int r = r0w + mt * 16 + eh * 8;
            const float* rp = (const float*)(smc + S_RMAX + r * 4 * 4);
            M[mt][eh] = fmaxf(fmaxf(rp[0], rp[1]), fmaxf(rp[2], rp[3]));
        }

    // ---- exp + row sum ----
    float ps[2][2] = {{0.f, 0.f}, {0.f, 0.f}};
#pragma unroll
    for (int mt = 0; mt < 2; mt++)
#pragma unroll
        for (int nt = 0; nt < 10; nt++)
#pragma unroll
            for (int e = 0; e < 4; e++) {
                const float ex = __expf(c1[mt][nt][e] - M[mt][e >> 1]);
                c1[mt][nt][e] = ex;
                ps[mt][e >> 1] += ex;
            }
#pragma unroll
    for (int mt = 0; mt < 2; mt++)
#pragma unroll
        for (int eh = 0; eh < 2; eh++) {
            ps[mt][eh] += __shfl_xor_sync(0xffffffffu, ps[mt][eh], 1);
            ps[mt][eh] += __shfl_xor_sync(0xffffffffu, ps[mt][eh], 2);
        }
    if (lanem == 0) {
#pragma unroll
        for (int mt = 0; mt < 2; mt++)
#pragma unroll
            for (int eh = 0; eh < 2; eh++) {
                const int r = r0w + mt * 16 + eh * 8;
                *(float*)(smc + S_RSUM + (r * 4 + nw) * 4) = ps[mt][eh];
            }
    }
    __syncthreads();

    // ---- p = e/sum; write probs gmem + bf16 hi/lo P smem ----
#pragma unroll
    for (int mt = 0; mt < 2; mt++)
#pragma unroll
        for (int eh = 0; eh < 2; eh++) {
            const int r = r0w + mt * 16 + eh * 8;
            const float* sp = (const float*)(smc + S_RSUM + r * 4 * 4);
            const float inv = 1.f / (sp[0] + sp[1] + sp[2] + sp[3]);
            float* prow = probs + ((size_t)bh * SEQ + (s0 + r)) * WIN;
            const uint32_t vbits = vb[mt][eh];
            char* pbh = smc + S_PH + r * PSTB;
            char* pbl = smc + S_PL + r * PSTB;
#pragma unroll
            for (int nt = 0; nt < 10; nt++) {
                float p0 = c1[mt][nt][eh * 2 + 0] * inv;
                float p1 = c1[mt][nt][eh * 2 + 1] * inv;
                if (!(vbits & (1u << (nt * 2 + 0)))) p0 = 0.f;
                if (!(vbits & (1u << (nt * 2 + 1)))) p1 = 0.f;
                const int cc = c0w + nt * 8;
                if (cc >= r && cc <= r + 256)         prow[cc - r]     = p0;
                if (cc + 1 >= r && cc + 1 <= r + 256) prow[cc + 1 - r] = p1;
                __nv_bfloat162 hh, ll;
                hh.x = __float2bfloat16(p0);
                hh.y = __float2bfloat16(p1);
                ll.x = __float2bfloat16(p0 - __bfloat162float(hh.x));
                ll.y = __float2bfloat16(p1 - __bfloat162float(hh.y));
                *(__nv_bfloat162*)(pbh + cc * 2) = hh;
                *(__nv_bfloat162*)(pbl + cc * 2) = ll;
            }
        }

    CP_WAIT0();
    __syncthreads();   // P smem visible + V staged

    // ---- GEMM2: O = P V (bf16x3), warps 4(m) x 2(n) ----
    const int mw2 = warp >> 1;       // 0..3
    const int nw2 = warp & 1;        // 0..1
    float c2[4][4];
#pragma unroll
    for (int j = 0; j < 4; j++)
#pragma unroll
        for (int e = 0; e < 4; e++) c2[j][e] = 0.f;

    const uint32_t pa_off = (uint32_t)(lane & 15) * PSTB + (uint32_t)(lane >> 4) * 16;
    const uint32_t vrow   = (lane & 7) + (((lane >> 3) & 1) << 3);
    const uint32_t vcoff  = (uint32_t)(nw2 * 32 + ((lane >> 4) << 3)) * 2;

#pragma unroll 4
    for (int kt = 0; kt < 20; kt++) {
        uint32_t Ph[4], Pl[4];
        const uint32_t pa = sb + S_PH + (uint32_t)(mw2 * 16) * PSTB + pa_off + kt * 32;
        ldm_x4(Ph, pa);
        ldm_x4(Pl, pa + (S_PL - S_PH));

        uint32_t vh0[4], vh1[4], vl0[4], vl1[4];
        const uint32_t va = sb + S_KH + (kt * 16 + vrow) * KSTB + vcoff;
        ldm_x4_t(vh0, va);
        ldm_x4_t(vh1, va + 32);
        ldm_x4_t(vl0, va + (S_KL - S_KH));
        ldm_x4_t(vl1, va + (S_KL - S_KH) + 32);

#pragma unroll
        for (int nt = 0; nt < 4; nt++) {
            const uint32_t* ph = (nt < 2) ? vh0 : vh1;
            const uint32_t* pl = (nt < 2) ? vl0 : vl1;
            const int j = nt & 1;
            mma_bf16(c2[nt], Ph, ph[2 * j], ph[2 * j + 1]);
            mma_bf16(c2[nt], Pl, ph[2 * j], ph[2 * j + 1]);
            mma_bf16(c2[nt], Ph, pl[2 * j], pl[2 * j + 1]);
        }
    }

    // ---- out epilogue ----
#pragma unroll
    for (int nt = 0; nt < 4; nt++) {
        const int d = nw2 * 32 + nt * 8 + 2 * lanem;
#pragma unroll
        for (int eh = 0; eh < 2; eh++) {
            const int r = mw2 * 16 + lane4 + eh * 8;
            *(float2*)(out + ((size_t)(s0 + r) * BATCH + b) * HID + head * HD + d) =
                make_float2(c2[nt][eh * 2], c2[nt][eh * 2 + 1]);
        }
    }
}

// ---------------- launch ------------------------------------------------------
extern "C" void kernel_launch(void* const* d_in, const int* in_sizes, int n_in,
                              void* d_out, int out_size)
{
    const float* q_in = (const float*)d_in[0];
    const float* k_in = (const float*)d_in[1];
    const float* v_in = (const float*)d_in[2];
    const unsigned char* mask = (const unsigned char*)d_in[3];
    const float* Wq = (const float*)d_in[4];
    const float* bq = (const float*)d_in[5];
    const float* Wk = (const float*)d_in[6];
    const float* bk = (const float*)d_in[7];
    const float* Wv = (const float*)d_in[8];
    const float* bv = (const float*)d_in[9];

    float* out   = (float*)d_out;
    float* probs = out + (size_t)SEQ * BATCH * HID;

    cudaFuncSetAttribute(proj_mma_kernel, cudaFuncAttributeMaxDynamicSharedMemorySize,
                         PROJ_SMEM);
    cudaFuncSetAttribute(attn_kernel, cudaFuncAttributeMaxDynamicSharedMemorySize,
                         ATT_SMEM);

    dim3 gx(ROWS * HID / 4 / 256, 3);
    convert_x<<<gx, 256>>>(q_in, k_in, v_in);
    dim3 gw(HID * HID / 4 / 256, 3);
    convert_w<<<gw, 256>>>(Wq, Wk, Wv);

    dim3 gp(HID / PBN, ROWS / PBM, 3);
    proj_mma_kernel<<<gp, 256, PROJ_SMEM>>>(bq, bk, bv);

    dim3 ga(SEQ / TQ, BHD);
    attn_kernel<<<ga, 256, ATT_SMEM>>>(mask, out, probs);
}